// round 8
// baseline (speedup 1.0000x reference)
#include <cuda_runtime.h>

// SSKernelDiag: out[h,l] = 2 * Re( sum_n Cc[h,n] * A[h,n]^l )
//   A = exp(abslog + i*phase), dtA = abslog + i*phase, Cc = C*(A-1)/dtA
// H=256, N=64, L=4096, CH=1.
//
// R8: no smem staging. n-split WITHIN the warp: lanes 0-15 own n[0,32),
// lanes 16-31 own n[32,64); pair (u, u^16) owns l = 32*tl + 2u + {0,1}.
// Per tile: 16 LDS.128 (broadcast) + 64 FFMA2 + 2 shfl.xor + 1 STG.32
// straight to gmem. One __syncthreads total. q(2u), q(2u+1) packed in regs.

#define HH 256
#define NN 64
#define LL 4096
#define CHUNKS 2
#define LCHUNK 2048
#define NTILES 64          // tiles of 32 l per chunk
#define NTHREADS 128
#define NH 32              // n per lane-half

typedef unsigned long long ull;

__device__ __forceinline__ float2 cmul(float2 a, float2 b) {
    return make_float2(fmaf(a.x, b.x, -(a.y * b.y)),
                       fmaf(a.x, b.y,  (a.y * b.x)));
}

// exp(i*y), 2-term Cody-Waite reduction; accurate for |y| <~ 2^14.
__device__ __forceinline__ float2 cis_cw(float y) {
    float m = rintf(y * 0.15915494309189535f);
    float r = fmaf(m, -6.28125f, y);          // 2*pi hi (exact in fp32)
    r = fmaf(m, -1.9353072e-3f, r);           // 2*pi lo
    float s, c;
    __sincosf(r, &s, &c);
    return make_float2(c, s);
}

__device__ __forceinline__ ull pack2(float x, float y) {
    ull r;
    asm("mov.b64 %0, {%1, %2};" : "=l"(r) : "f"(x), "f"(y));
    return r;
}
__device__ __forceinline__ float2 unpack2(ull v) {
    float x, y;
    asm("mov.b64 {%0, %1}, %2;" : "=f"(x), "=f"(y) : "l"(v));
    return make_float2(x, y);
}
__device__ __forceinline__ void ffma2(ull& acc, ull a, ull b) {
    asm("fma.rn.f32x2 %0, %1, %2, %0;" : "+l"(acc) : "l"(a), "l"(b));
}
__device__ __forceinline__ ull fadd2(ull a, ull b) {
    ull r;
    asm("add.rn.f32x2 %0, %1, %2;" : "=l"(r) : "l"(a), "l"(b));
    return r;
}

__global__ void __launch_bounds__(NTHREADS, 3)
ssk_diag_kernel(const float* __restrict__ abslog,
                const float* __restrict__ phase,
                const float* __restrict__ C,
                float* __restrict__ out) {
    __shared__ float2 sW[NTILES][NN];     // 32 KB: W[tl][n] = 2 Cc A^(l0+32 tl)
    __shared__ float2 qtab[NN][12];       // 6 KB: A^j (j<8), A^(8(j-8)) (j>=8)

    const int bid   = blockIdx.x;
    const int h     = bid >> 1;
    const int chunk = bid & 1;
    const int tid   = threadIdx.x;
    const int warp  = tid >> 5;
    const int lane  = tid & 31;
    const int u     = lane & 15;          // l-pair index within tile
    const int half  = lane >> 4;          // n half: 0 -> n[0,32), 1 -> n[32,64)

    const float* alh = abslog + h * NN;
    const float* phh = phase  + h * NN;
    const float  l0f = (float)(chunk * LCHUNK);

    // ---- phase A: qtab[n][j] = A^j (j<8) | A^(8*(j-8)) (8<=j<12) ----
    #pragma unroll
    for (int k = 0; k < 6; k++) {
        const int e = tid + k * NTHREADS;     // 768 entries = 64 n x 12
        const int n = e / 12;
        const int j = e % 12;
        const float f  = (j < 8) ? (float)j : (float)(8 * (j - 8));
        const float al = alh[n];
        const float ph = phh[n];
        float2 cs = cis_cw(ph * f);
        float  ex = __expf(al * f);
        qtab[n][j] = make_float2(ex * cs.x, ex * cs.y);
    }

    // ---- phase B: W table; per (n, oct) two depth-16 chains, step A^32 ----
    {
        const int n   = tid & (NN - 1);
        const int oct = tid >> 6;             // [0,2)
        const float al = alh[n];
        const float ph = phh[n];

        float er = __expf(al);
        float s0, c0;
        __sincosf(ph, &s0, &c0);
        float2 Am1 = make_float2(er * c0 - 1.0f, er * s0);
        float2 Cin = reinterpret_cast<const float2*>(C)[h * NN + n];
        float2 num = cmul(Cin, Am1);
        float  inv = 1.0f / fmaf(al, al, ph * ph);
        float2 Cc;
        Cc.x = 2.0f * (num.x * al + num.y * ph) * inv;
        Cc.y = 2.0f * (num.y * al - num.x * ph) * inv;

        float2 A32 = cis_cw(ph * 32.0f);
        float  E32 = __expf(al * 32.0f);
        A32.x *= E32; A32.y *= E32;

        #pragma unroll
        for (int seg = 0; seg < 2; seg++) {
            const float e0 = l0f + 1024.0f * (float)oct + 512.0f * (float)seg;
            float2 cs = cis_cw(ph * e0);
            float  E0 = __expf(al * e0);
            float2 P  = make_float2(E0 * cs.x, E0 * cs.y);
            const int base = 32 * oct + 16 * seg;
            #pragma unroll
            for (int s = 0; s < 16; s++) {
                sW[base + s][n] = cmul(Cc, P);
                P = cmul(P, A32);
            }
        }
    }
    __syncthreads();

    // ---- phase C: register q for this lane's 32 n and 2 l-offsets ----
    // q0 = A^(2u) = A^(8a) * A^b ; q1 = q0 * A
    ull qp0[NH], qp1[NH];
    {
        const int jlo = (2 * u) & 7;
        const int jhi = 8 + ((2 * u) >> 3);
        #pragma unroll
        for (int i = 0; i < NH; i++) {
            const int n = half * NH + i;
            float2 lo = qtab[n][jlo];
            float2 hi = qtab[n][jhi];
            float2 a1 = qtab[n][1];
            float2 q0 = cmul(hi, lo);
            float2 q1 = cmul(q0, a1);
            qp0[i] = pack2(q0.x, -q0.y);   // (re,-im): Re(w*q) = elementwise dot
            qp1[i] = pack2(q1.x, -q1.y);
        }
    }

    // ---- main: 16 tiles/warp x [16 LDS.128 + 64 FFMA2 + 2 shfl + 1 STG] ----
    const ull zero = pack2(0.0f, 0.0f);
    float* outc = out + h * LL + chunk * LCHUNK;

    #pragma unroll 2
    for (int tl = warp; tl < NTILES; tl += 4) {
        const ulonglong2* w =
            reinterpret_cast<const ulonglong2*>(&sW[tl][half * NH]);
        ull a0 = zero, a1 = zero, b0 = zero, b1 = zero;
        #pragma unroll
        for (int i = 0; i < NH / 2; i++) {
            ulonglong2 wi = w[i];                 // 2 complex W (n=2i, 2i+1)
            ffma2(a0, wi.x, qp0[2 * i]);
            ffma2(b0, wi.x, qp1[2 * i]);
            ffma2(a1, wi.y, qp0[2 * i + 1]);
            ffma2(b1, wi.y, qp1[2 * i + 1]);
        }
        float2 ua = unpack2(fadd2(a0, a1));
        float2 ub = unpack2(fadd2(b0, b1));
        float s0 = ua.x + ua.y;                   // l = 32*tl + 2u
        float s1 = ub.x + ub.y;                   // l = 32*tl + 2u + 1
        s0 += __shfl_xor_sync(0xffffffffu, s0, 16);
        s1 += __shfl_xor_sync(0xffffffffu, s1, 16);
        outc[32 * tl + 2 * u + half] = half ? s1 : s0;
    }
}

extern "C" void kernel_launch(void* const* d_in, const int* in_sizes, int n_in,
                              void* d_out, int out_size) {
    const float* abslog = (const float*)d_in[0];  // (H, N) f32
    const float* phase  = (const float*)d_in[1];  // (H, N) f32
    const float* C      = (const float*)d_in[2];  // (1, H, N, 2) f32
    float* out = (float*)d_out;                   // (1, H, L) f32

    ssk_diag_kernel<<<HH * CHUNKS, NTHREADS>>>(abslog, phase, C, out);
}

// round 9
// speedup vs baseline: 1.2278x; 1.2278x over previous
#include <cuda_runtime.h>

// SSKernelDiag: out[h,l] = 2 * Re( sum_n Cc[h,n] * A[h,n]^l )
//   A = exp(abslog + i*phase), dtA = abslog + i*phase, Cc = C*(A-1)/dtA
// H=256, N=64, L=4096, CH=1.
//
// R9: decay-aware truncation. |A^l| = exp(abslog*l) with abslog<0; terms with
// |A|^l < e^-23 (~1e-10) are dropped. Per head: sort n by l_cut desc, so each
// 32-l tile's active set is a rank prefix. Warp w owns tiles {w, w+8, ...}
// with per-lane W recurrence (step A^256) staged to smem per tile; inner loop
// over active ranks: 2 LDS.128 (W) + 4 LDS.64 (q) + 4 FFMA2 per 4 ranks.

#define HH 256
#define NN 64
#define LL 4096
#define TILE 32
#define NTILES 128
#define NTHREADS 256
#define NWARPS 8
#define TPW 16            // tiles per warp
#define CUT 23.0f         // e^-23 ~ 1e-10 magnitude cutoff

typedef unsigned long long ull;

__device__ __forceinline__ float2 cmul(float2 a, float2 b) {
    return make_float2(fmaf(a.x, b.x, -(a.y * b.y)),
                       fmaf(a.x, b.y,  (a.y * b.x)));
}
// exp(i*y), 2-term Cody-Waite reduction; accurate for |y| <~ 2^14.
__device__ __forceinline__ float2 cis_cw(float y) {
    float m = rintf(y * 0.15915494309189535f);
    float r = fmaf(m, -6.28125f, y);
    r = fmaf(m, -1.9353072e-3f, r);
    float s, c;
    __sincosf(r, &s, &c);
    return make_float2(c, s);
}
// A^f = exp(al*f) * cis(ph*f)
__device__ __forceinline__ float2 apow(float al, float ph, float f) {
    float2 cs = cis_cw(ph * f);
    float  e  = __expf(al * f);
    return make_float2(e * cs.x, e * cs.y);
}
__device__ __forceinline__ ull pack2(float x, float y) {
    ull r;
    asm("mov.b64 %0, {%1, %2};" : "=l"(r) : "f"(x), "f"(y));
    return r;
}
__device__ __forceinline__ float2 unpack2(ull v) {
    float x, y;
    asm("mov.b64 {%0, %1}, %2;" : "=f"(x), "=f"(y) : "l"(v));
    return make_float2(x, y);
}
__device__ __forceinline__ void ffma2(ull& acc, ull a, ull b) {
    asm("fma.rn.f32x2 %0, %1, %2, %0;" : "+l"(acc) : "l"(a), "l"(b));
}

__global__ void __launch_bounds__(NTHREADS, 2)
ssk_diag_kernel(const float* __restrict__ abslog,
                const float* __restrict__ phase,
                const float* __restrict__ C,
                float* __restrict__ out) {
    __shared__ float  alR[NN], phR[NN];     // rank-indexed params
    __shared__ float2 CcR[NN];              // rank-indexed 2*Cc
    __shared__ int    lcut[NN];             // by n
    __shared__ int    srt[NN];              // rank -> n
    __shared__ int    cnt4[NTILES];         // active ranks per tile, ceil to 4
    __shared__ float2 sQr[NN][TILE];        // 16 KB: (qr, -qi) = conj A^t, rank idx
    __shared__ float2 sWbuf[NWARPS][NN];    // 4 KB: per-warp W staging

    const int h    = blockIdx.x;
    const int tid  = threadIdx.x;
    const int warp = tid >> 5;
    const int lane = tid & 31;

    const float* alh = abslog + h * NN;
    const float* phh = phase  + h * NN;

    // ---- 1: l_cut per n ----
    if (tid < NN) {
        const float al = alh[tid];
        float lc = fminf((float)LL, CUT / (-al) + 1.0f);
        lcut[tid] = (int)lc;
    }
    __syncthreads();

    // ---- 2: rank (desc by l_cut, index tiebreak) + per-tile counts ----
    if (tid < NN) {
        const int my = lcut[tid];
        int rank = 0;
        #pragma unroll 8
        for (int m = 0; m < NN; m++) {
            const int o = lcut[m];
            rank += (o > my) || (o == my && m < tid);
        }
        srt[rank] = tid;
    }
    if (tid >= 128) {
        const int tl = tid - 128;
        const int lmin = TILE * tl;
        int c = 0;
        #pragma unroll 8
        for (int m = 0; m < NN; m++) c += (lcut[m] > lmin);
        cnt4[tl] = (c + 3) & ~3;
    }
    __syncthreads();

    // ---- 3: rank-indexed params + Cc ----
    if (tid < NN) {
        const int n = srt[tid];
        const float al = alh[n];
        const float ph = phh[n];
        alR[tid] = al;
        phR[tid] = ph;
        float er = __expf(al);
        float s0, c0;
        __sincosf(ph, &s0, &c0);
        float2 Am1 = make_float2(er * c0 - 1.0f, er * s0);
        float2 Cin = reinterpret_cast<const float2*>(C)[h * NN + n];
        float2 num = cmul(Cin, Am1);
        float  inv = 1.0f / fmaf(al, al, ph * ph);
        float2 Cc;
        Cc.x = 2.0f * (num.x * al + num.y * ph) * inv;
        Cc.y = 2.0f * (num.y * al - num.x * ph) * inv;
        CcR[tid] = Cc;
    }
    __syncthreads();

    // ---- 4: sQr[r][t] = conj-packed A^t (t in [0,32)); thread = (r, q8) ----
    {
        const int r  = tid & 63;
        const int q8 = tid >> 6;              // [0,4): t block of 8
        const float al = alR[r];
        const float ph = phR[r];
        float2 P  = apow(al, ph, 8.0f * (float)q8);
        float2 A1 = apow(al, ph, 1.0f);
        #pragma unroll
        for (int j = 0; j < 8; j++) {
            sQr[r][8 * q8 + j] = make_float2(P.x, -P.y);
            P = cmul(P, A1);
        }
    }

    // ---- 5: per-lane W recurrence state (ranks lane, lane+32) ----
    float2 W0, W1, S0, S1;
    {
        const float a0 = alR[lane],      p0 = phR[lane];
        const float a1 = alR[lane + 32], p1 = phR[lane + 32];
        const float e0 = (float)(TILE * warp);   // first tile = warp
        W0 = cmul(CcR[lane],      apow(a0, p0, e0));
        W1 = cmul(CcR[lane + 32], apow(a1, p1, e0));
        S0 = apow(a0, p0, 256.0f);               // step = 8 warps * 32 l
        S1 = apow(a1, p1, 256.0f);
    }
    __syncthreads();

    // ---- main: 16 strided tiles per warp ----
    float* outh = out + h * LL;
    const ulonglong2* wb = reinterpret_cast<const ulonglong2*>(sWbuf[warp]);

    for (int k = 0; k < TPW; k++) {
        const int tl = warp + NWARPS * k;
        __syncwarp();
        sWbuf[warp][lane]      = W0;
        sWbuf[warp][lane + 32] = W1;
        __syncwarp();

        const int m = cnt4[tl];
        ull acc = pack2(0.0f, 0.0f);
        for (int r = 0; r < m; r += 4) {
            ulonglong2 wa = wb[(r >> 1)];
            ulonglong2 wc = wb[(r >> 1) + 1];
            ull q0 = *reinterpret_cast<const ull*>(&sQr[r + 0][lane]);
            ull q1 = *reinterpret_cast<const ull*>(&sQr[r + 1][lane]);
            ull q2 = *reinterpret_cast<const ull*>(&sQr[r + 2][lane]);
            ull q3 = *reinterpret_cast<const ull*>(&sQr[r + 3][lane]);
            ffma2(acc, wa.x, q0);
            ffma2(acc, wa.y, q1);
            ffma2(acc, wc.x, q2);
            ffma2(acc, wc.y, q3);
        }
        float2 u = unpack2(acc);
        outh[TILE * tl + lane] = u.x + u.y;

        W0 = cmul(W0, S0);
        W1 = cmul(W1, S1);
    }
}

extern "C" void kernel_launch(void* const* d_in, const int* in_sizes, int n_in,
                              void* d_out, int out_size) {
    const float* abslog = (const float*)d_in[0];  // (H, N) f32
    const float* phase  = (const float*)d_in[1];  // (H, N) f32
    const float* C      = (const float*)d_in[2];  // (1, H, N, 2) f32
    float* out = (float*)d_out;                   // (1, H, L) f32

    ssk_diag_kernel<<<HH, NTHREADS>>>(abslog, phase, C, out);
}